// round 8
// baseline (speedup 1.0000x reference)
#include <cuda_runtime.h>
#include <cuda_fp16.h>
#include <cstdint>

// ============================================================================
// GraphConvolutionSparse: out = adj @ (inputs @ W)
// R8: GEMM2 k-split warp groups. Two 4-warp groups per CTA, each owns half of
// K with its own 3-stage KTG=32 pipeline + 128-thread named barrier. Warp tile
// 32x64 (A-LDSM redundancy 4x -> 2x). Smem reduction combines the halves.
// GEMM1 unchanged from R7 (proven).
// ============================================================================

#define N_ROWS 16384
#define D_IN   512
#define D_OUT  128

// ---- GEMM2 geometry ----
#define MT2 64
#define NT2 128
#define KTG 32
#define NST2 3
#define A2_BYTES (MT2 * 64)                  // 64 rows x 64B fp16 = 4KB
#define B2_BYTES (NT2 * 64)                  // 128 rows x 64B fp16 = 8KB
#define STG2_BYTES (A2_BYTES + B2_BYTES)     // 12KB
#define GRP_BYTES (NST2 * STG2_BYTES)        // 36KB
#define SMEM2 (2 * GRP_BYTES)                // 72KB (also covers 33KB reduce)

// ---- GEMM1 geometry (R7) ----
#define MT1 64
#define KT1 64
#define NST1 3
#define STG1_BYTES (MT1 * 128 + 128 * 128)   // A 8KB + B 16KB
#define SMEM1 (NST1 * STG1_BYTES)            // 72KB

__device__ unsigned short g_xT[D_OUT * N_ROWS];   // x transposed, fp16 bits

// ---------------- helpers ----------------
static __device__ __forceinline__ uint32_t smem_u32(const void* p) {
    uint32_t a;
    asm("{ .reg .u64 t; cvta.to.shared.u64 t, %1; cvt.u32.u64 %0, t; }"
        : "=r"(a) : "l"(p));
    return a;
}
static __device__ __forceinline__ uint32_t pack2(float lo, float hi) {
    __half2 h = __floats2half2_rn(lo, hi);
    return *reinterpret_cast<uint32_t*>(&h);
}
static __device__ __forceinline__ void sts64(uint32_t a, uint32_t u0, uint32_t u1) {
    asm volatile("st.shared.v2.b32 [%0], {%1,%2};" :: "r"(a), "r"(u0), "r"(u1) : "memory");
}
static __device__ __forceinline__ void sts16(uint32_t a, unsigned short h) {
    asm volatile("st.shared.u16 [%0], %1;" :: "r"(a), "h"(h) : "memory");
}
static __device__ __forceinline__ void cp16(uint32_t dst, const void* src) {
    asm volatile("cp.async.cg.shared.global [%0], [%1], 16;"
                 :: "r"(dst), "l"(src) : "memory");
}
static __device__ __forceinline__ void cp_commit() {
    asm volatile("cp.async.commit_group;" ::: "memory");
}
static __device__ __forceinline__ void cp_wait1() {
    asm volatile("cp.async.wait_group 1;" ::: "memory");
}
static __device__ __forceinline__ void barg(int id) {
    asm volatile("bar.sync %0, 128;" :: "r"(id) : "memory");
}
static __device__ __forceinline__ void ldsm_x4(uint32_t* r, uint32_t addr) {
    asm volatile("ldmatrix.sync.aligned.m8n8.x4.shared.b16 {%0,%1,%2,%3}, [%4];"
                 : "=r"(r[0]), "=r"(r[1]), "=r"(r[2]), "=r"(r[3]) : "r"(addr));
}
static __device__ __forceinline__ void mma16816(float* c, const uint32_t* a,
                                                uint32_t b0, uint32_t b1) {
    asm volatile(
        "mma.sync.aligned.m16n8k16.row.col.f32.f16.f16.f32 "
        "{%0,%1,%2,%3}, {%4,%5,%6,%7}, {%8,%9}, {%0,%1,%2,%3};"
        : "+f"(c[0]), "+f"(c[1]), "+f"(c[2]), "+f"(c[3])
        : "r"(a[0]), "r"(a[1]), "r"(a[2]), "r"(a[3]), "r"(b0), "r"(b1));
}

// ============================================================================
// GEMM2: out = adj @ x.  64B-row swizzle: chunk16' = chunk ^ ((row>>1)&3).
// ============================================================================
__global__ void __launch_bounds__(256, 2)
gcn_gemm2(const float* __restrict__ A, float* __restrict__ Out)
{
    extern __shared__ char smem[];
    const uint32_t sb = smem_u32(smem);
    const int tid  = threadIdx.x;
    const int lane = tid & 31;
    const int wid  = tid >> 5;
    const int grp  = wid >> 2;               // 0 or 1 (k-half)
    const int gtid = tid & 127;
    const int lw   = wid & 3;                // warp within group
    const int m0   = blockIdx.x * MT2;
    const long kbase = (long)grp * (N_ROWS / 2);
    const int iters  = (N_ROWS / 2) / KTG;   // 256
    const uint32_t gb = sb + grp * GRP_BYTES;

    const int warpM = (lw & 1) * 32;
    const int warpN = (lw >> 1) * 64;

    // A staging: 64 rows x 32 f32, 2 threads/row x 16 floats
    const int arow = gtid >> 1;
    const int aq   = gtid & 1;

    float4 af[4];
    auto load_regs = [&](int i) {
        const long k0 = kbase + (long)i * KTG;
        const float* src = A + (long)(m0 + arow) * N_ROWS + k0 + aq * 16;
        #pragma unroll
        for (int j = 0; j < 4; j++)
            af[j] = *reinterpret_cast<const float4*>(src + j * 4);
    };

    auto produce = [&](int i) {
        const int st = i % NST2;
        const uint32_t ab = gb + st * STG2_BYTES;
        const uint32_t bb = ab + A2_BYTES;
        #pragma unroll
        for (int j = 0; j < 4; j++) {
            const int chunk = 2 * aq + (j >> 1);
            const uint32_t addr = ab + arow * 64
                + ((chunk ^ ((arow >> 1) & 3)) << 4) + (j & 1) * 8;
            sts64(addr, pack2(af[j].x, af[j].y), pack2(af[j].z, af[j].w));
        }
        const long k0 = kbase + (long)i * KTG;
        const unsigned short* src = g_xT + (long)gtid * N_ROWS + k0;
        #pragma unroll
        for (int j = 0; j < 4; j++)
            cp16(bb + gtid * 64 + ((j ^ ((gtid >> 1) & 3)) << 4), src + j * 8);
    };

    float c[2][8][4];
    #pragma unroll
    for (int mi = 0; mi < 2; mi++)
        #pragma unroll
        for (int nj = 0; nj < 8; nj++)
            #pragma unroll
            for (int q = 0; q < 4; q++) c[mi][nj][q] = 0.f;

    const int rowA_l = warpM + (lane & 15);
    const int cpA    = lane >> 4;
    const int rowB_l = warpN + (lane & 7) + 8 * (lane >> 4);
    const int cpB    = (lane >> 3) & 1;

    auto compute = [&](int i) {
        const int st = i % NST2;
        const uint32_t ab = gb + st * STG2_BYTES;
        const uint32_t bb = ab + A2_BYTES;
        #pragma unroll
        for (int ks = 0; ks < 2; ks++) {
            uint32_t a[2][4];
            #pragma unroll
            for (int mi = 0; mi < 2; mi++) {
                const int r = rowA_l + mi * 16;
                const int ch = 2 * ks + cpA;
                ldsm_x4(a[mi], ab + r * 64 + ((ch ^ ((r >> 1) & 3)) << 4));
            }
            uint32_t b[4][4];
            #pragma unroll
            for (int nb = 0; nb < 4; nb++) {
                const int r = rowB_l + nb * 16;
                const int ch = 2 * ks + cpB;
                ldsm_x4(b[nb], bb + r * 64 + ((ch ^ ((r >> 1) & 3)) << 4));
            }
            #pragma unroll
            for (int mi = 0; mi < 2; mi++)
                #pragma unroll
                for (int nb = 0; nb < 4; nb++) {
                    mma16816(c[mi][nb * 2 + 0], a[mi], b[nb][0], b[nb][1]);
                    mma16816(c[mi][nb * 2 + 1], a[mi], b[nb][2], b[nb][3]);
                }
        }
    };

    // ---- per-group pipeline: 3-stage, one 128-thread named barrier/iter ----
    load_regs(0);
    produce(0);
    cp_commit();
    load_regs(1);

    for (int i = 0; i < iters; i++) {
        if (i + 1 < iters) produce(i + 1);
        cp_commit();
        if (i + 2 < iters) load_regs(i + 2);
        cp_wait1();
        barg(1 + grp);
        compute(i);
    }

    // ---- combine k-halves: grp1 -> smem, grp0 adds + stores ----
    __syncthreads();
    const int erow_l = warpM + (lane >> 2);
    const int ecol   = warpN + (lane & 3) * 2;
    float* red = reinterpret_cast<float*>(smem);
    if (grp == 1) {
        #pragma unroll
        for (int mi = 0; mi < 2; mi++)
            #pragma unroll
            for (int nj = 0; nj < 8; nj++) {
                const int rl = erow_l + mi * 16;
                const int n  = ecol + nj * 8;
                float* s = red + rl * 132 + n;
                s[0] = c[mi][nj][0];
                s[1] = c[mi][nj][1];
                s[132 * 8 + 0] = c[mi][nj][2];
                s[132 * 8 + 1] = c[mi][nj][3];
            }
    }
    __syncthreads();
    if (grp == 0) {
        #pragma unroll
        for (int mi = 0; mi < 2; mi++)
            #pragma unroll
            for (int nj = 0; nj < 8; nj++) {
                const int rl = erow_l + mi * 16;
                const int n  = ecol + nj * 8;
                const float* s = red + rl * 132 + n;
                const long r = m0 + rl;
                *reinterpret_cast<float2*>(Out + r * NT2 + n) =
                    make_float2(c[mi][nj][0] + s[0], c[mi][nj][1] + s[1]);
                *reinterpret_cast<float2*>(Out + (r + 8) * NT2 + n) =
                    make_float2(c[mi][nj][2] + s[132 * 8],
                                c[mi][nj][3] + s[132 * 8 + 1]);
            }
    }
}

// ============================================================================
// GEMM1 (unchanged R7 design): xT = (inputs @ W)^T -> g_xT fp16
// CTA 64x128, K-tile 64, 8 warps 32x32, 3-stage, one barrier/iter.
// ============================================================================
__global__ void __launch_bounds__(256, 2)
gcn_gemm1(const float* __restrict__ A, const float* __restrict__ W)
{
    extern __shared__ char smem[];
    const uint32_t sb = smem_u32(smem);
    const int tid = threadIdx.x;
    const int lane = tid & 31;
    const int wid = tid >> 5;
    const int m0 = blockIdx.x * MT1;
    const int warpM = (wid & 1) * 32;
    const int warpN = (wid >> 1) * 32;
    const int iters = D_IN / KT1;        // 8

    float4 af[4];
    float4 bw[8];
    const int msub = tid >> 4;
    const int kq   = tid & 15;
    const int nq = (tid & 31) * 4;
    const int kk = tid >> 5;

    auto load_regs = [&](int i) {
        const long k0 = (long)i * KT1;
        #pragma unroll
        for (int j = 0; j < 4; j++) {
            const int m = msub + 16 * j;
            af[j] = *reinterpret_cast<const float4*>(A + (long)(m0 + m) * D_IN + k0 + kq * 4);
        }
        #pragma unroll
        for (int j = 0; j < 8; j++) {
            const long k = k0 + kk + 8 * j;
            bw[j] = *reinterpret_cast<const float4*>(W + k * 128 + nq);
        }
    };

    auto produce = [&](int i) {
        const int stage = i % NST1;
        const uint32_t abase = sb + stage * STG1_BYTES;
        const uint32_t bbase = abase + MT1 * 128;
        #pragma unroll
        for (int j = 0; j < 4; j++) {
            const int m = msub + 16 * j;
            const uint32_t addr = abase + m * 128
                + ((((kq * 4) >> 3) ^ (m & 7)) << 4) + ((kq & 1) << 3);
            sts64(addr, pack2(af[j].x, af[j].y), pack2(af[j].z, af[j].w));
        }
        #pragma unroll
        for (int j = 0; j < 8; j++) {
            const float* f = &bw[j].x;
            #pragma unroll
            for (int q = 0; q < 4; q++) {
                const int n = nq + q;
                const uint32_t addr = bbase + n * 128
                    + ((j ^ (n & 7)) << 4) + (kk << 1);
                sts16(addr, __half_as_ushort(__float2half_rn(f[q])));
            }
        }
    };

    float c[2][4][4];
    #pragma unroll
    for (int mi = 0; mi < 2; mi++)
        #pragma unroll
        for (int nj = 0; nj < 4; nj++)
            #pragma unroll
            for (int q = 0; q < 4; q++) c[mi][nj][q] = 0.f;

    const int rowA  = warpM + (lane & 15);
    const int cpA   = lane >> 4;
    const int rowBb = warpN + (lane & 7) + 8 * (lane >> 4);
    const int rowB7 = rowBb & 7;
    const int cpB   = (lane >> 3) & 1;

    auto compute = [&](int i) {
        const int stage = i % NST1;
        const uint32_t abase = sb + stage * STG1_BYTES;
        const uint32_t bbase = abase + MT1 * 128;
        #pragma unroll
        for (int ks = 0; ks < 4; ks++) {
            uint32_t a[2][4];
            #pragma unroll
            for (int mi = 0; mi < 2; mi++)
                ldsm_x4(a[mi], abase + (rowA + mi * 16) * 128
                        + (((ks * 2 + cpA) ^ (rowA & 7)) << 4));
            uint32_t b[2][4];
            #pragma unroll
            for (int nbp = 0; nbp < 2; nbp++)
                ldsm_x4(b[nbp], bbase + (rowBb + nbp * 16) * 128
                        + (((ks * 2 + cpB) ^ rowB7) << 4));
            #pragma unroll
            for (int mi = 0; mi < 2; mi++)
                #pragma unroll
                for (int nbp = 0; nbp < 2; nbp++) {
                    mma16816(c[mi][nbp * 2 + 0], a[mi], b[nbp][0], b[nbp][1]);
                    mma16816(c[mi][nbp * 2 + 1], a[mi], b[nbp][2], b[nbp][3]);
                }
        }
    };

    load_regs(0);
    produce(0);
    if (iters > 1) load_regs(1);

    for (int i = 0; i < iters; i++) {
        if (i + 1 < iters) produce(i + 1);
        if (i + 2 < iters) load_regs(i + 2);
        __syncthreads();
        compute(i);
    }

    const int erow = m0 + warpM + (lane >> 2);
    const int ecol = warpN + (lane & 3) * 2;
    #pragma unroll
    for (int mi = 0; mi < 2; mi++) {
        #pragma unroll
        for (int nj = 0; nj < 4; nj++) {
            const int r = erow + mi * 16;
            const int n = ecol + nj * 8;
            const float* cc = c[mi][nj];
            g_xT[(long)n * N_ROWS + r]           = __half_as_ushort(__float2half_rn(cc[0]));
            g_xT[(long)(n + 1) * N_ROWS + r]     = __half_as_ushort(__float2half_rn(cc[1]));
            g_xT[(long)n * N_ROWS + r + 8]       = __half_as_ushort(__float2half_rn(cc[2]));
            g_xT[(long)(n + 1) * N_ROWS + r + 8] = __half_as_ushort(__float2half_rn(cc[3]));
        }
    }
}

// ============================================================================
extern "C" void kernel_launch(void* const* d_in, const int* in_sizes, int n_in,
                              void* d_out, int out_size)
{
    const float* inputs = nullptr;
    const float* adj = nullptr;
    const float* w = nullptr;
    for (int i = 0; i < n_in; i++) {
        if (in_sizes[i] == N_ROWS * D_IN)        inputs = (const float*)d_in[i];
        else if (in_sizes[i] == N_ROWS * N_ROWS) adj    = (const float*)d_in[i];
        else if (in_sizes[i] == D_IN * D_OUT)    w      = (const float*)d_in[i];
    }
    float* out = (float*)d_out;

    cudaFuncSetAttribute(gcn_gemm1,
                         cudaFuncAttributeMaxDynamicSharedMemorySize, SMEM1);
    cudaFuncSetAttribute(gcn_gemm2,
                         cudaFuncAttributeMaxDynamicSharedMemorySize, SMEM2);

    gcn_gemm1<<<N_ROWS / MT1, 256, SMEM1>>>(inputs, w);
    gcn_gemm2<<<N_ROWS / MT2, 256, SMEM2>>>(adj, out);
}

// round 9
// speedup vs baseline: 1.0462x; 1.0462x over previous
#include <cuda_runtime.h>
#include <cuda_fp16.h>
#include <cstdint>

// ============================================================================
// GraphConvolutionSparse: out = adj @ (inputs @ W)
// R9 GEMM2: warp-specialized producer/consumer pipeline.
//   warps 0-3: consumers (LDSM + MMA, warp tile 32x64), never LDG.
//   warps 4-7: producers (A LDG->cvt fp16->STS, B cp.async), absorb latency.
//   4-stage ring, full/empty mbarriers, no __syncthreads in the loop.
// GEMM1 unchanged (R7, proven).
// ============================================================================

#define N_ROWS 16384
#define D_IN   512
#define D_OUT  128

// ---- GEMM2 ----
#define MT2 64
#define NT2 128
#define KT2 64
#define NST2 4
#define A2_BYTES (MT2 * 128)                 // 64 rows x 128B fp16 = 8KB
#define B2_BYTES (NT2 * 128)                 // 128 rows x 128B fp16 = 16KB
#define STG2 (A2_BYTES + B2_BYTES)           // 24KB
#define SMEM2 (1024 + NST2 * STG2)           // 1KB ctrl + 96KB stages

// ---- GEMM1 (R7) ----
#define MT1 64
#define KT1 64
#define NST1 3
#define STG1 (MT1 * 128 + 128 * 128)         // 24KB
#define SMEM1 (NST1 * STG1)                  // 72KB

__device__ unsigned short g_xT[D_OUT * N_ROWS];   // x transposed, fp16 bits

// ---------------- helpers ----------------
static __device__ __forceinline__ uint32_t smem_u32(const void* p) {
    uint32_t a;
    asm("{ .reg .u64 t; cvta.to.shared.u64 t, %1; cvt.u32.u64 %0, t; }"
        : "=r"(a) : "l"(p));
    return a;
}
static __device__ __forceinline__ uint32_t pack2(float lo, float hi) {
    __half2 h = __floats2half2_rn(lo, hi);
    return *reinterpret_cast<uint32_t*>(&h);
}
static __device__ __forceinline__ void sts64(uint32_t a, uint32_t u0, uint32_t u1) {
    asm volatile("st.shared.v2.b32 [%0], {%1,%2};" :: "r"(a), "r"(u0), "r"(u1) : "memory");
}
static __device__ __forceinline__ void sts16(uint32_t a, unsigned short h) {
    asm volatile("st.shared.u16 [%0], %1;" :: "r"(a), "h"(h) : "memory");
}
static __device__ __forceinline__ void cp16(uint32_t dst, const void* src) {
    asm volatile("cp.async.cg.shared.global [%0], [%1], 16;"
                 :: "r"(dst), "l"(src) : "memory");
}
static __device__ __forceinline__ void mbar_init(uint32_t a, uint32_t cnt) {
    asm volatile("mbarrier.init.shared.b64 [%0], %1;" :: "r"(a), "r"(cnt) : "memory");
}
static __device__ __forceinline__ void mbar_arrive(uint32_t a) {
    asm volatile("mbarrier.arrive.shared.b64 _, [%0];" :: "r"(a) : "memory");
}
static __device__ __forceinline__ void cp_mbar_arrive(uint32_t a) {
    asm volatile("cp.async.mbarrier.arrive.noinc.shared.b64 [%0];" :: "r"(a) : "memory");
}
static __device__ __forceinline__ void mbar_wait(uint32_t a, uint32_t parity) {
    asm volatile(
        "{\n\t"
        ".reg .pred P;\n\t"
        "WAITL_%=:\n\t"
        "mbarrier.try_wait.parity.acquire.cta.shared::cta.b64 P, [%0], %1, 0x989680;\n\t"
        "@!P bra WAITL_%=;\n\t"
        "}"
        :: "r"(a), "r"(parity) : "memory");
}
static __device__ __forceinline__ void ldsm_x4(uint32_t* r, uint32_t addr) {
    asm volatile("ldmatrix.sync.aligned.m8n8.x4.shared.b16 {%0,%1,%2,%3}, [%4];"
                 : "=r"(r[0]), "=r"(r[1]), "=r"(r[2]), "=r"(r[3]) : "r"(addr));
}
static __device__ __forceinline__ void mma16816(float* c, const uint32_t* a,
                                                uint32_t b0, uint32_t b1) {
    asm volatile(
        "mma.sync.aligned.m16n8k16.row.col.f32.f16.f16.f32 "
        "{%0,%1,%2,%3}, {%4,%5,%6,%7}, {%8,%9}, {%0,%1,%2,%3};"
        : "+f"(c[0]), "+f"(c[1]), "+f"(c[2]), "+f"(c[3])
        : "r"(a[0]), "r"(a[1]), "r"(a[2]), "r"(a[3]), "r"(b0), "r"(b1));
}

// ============================================================================
// GEMM2: out = adj @ x    (warp-specialized)
// smem: [0,64)=mbarriers (full[4], empty[4]), stages at 1024.
// ============================================================================
__global__ void __launch_bounds__(256, 2)
gcn_gemm2(const float* __restrict__ A, float* __restrict__ Out)
{
    extern __shared__ char smem[];
    const uint32_t sb = smem_u32(smem);
    const int tid  = threadIdx.x;
    const int lane = tid & 31;
    const int wid  = tid >> 5;
    const int m0   = blockIdx.x * MT2;
    const int iters = N_ROWS / KT2;          // 256

    const uint32_t fullb  = sb;              // full[s]  = sb + 8s
    const uint32_t emptyb = sb + 32;         // empty[s] = sb + 32 + 8s
    const uint32_t stage0 = sb + 1024;

    if (tid == 0) {
        #pragma unroll
        for (int s = 0; s < NST2; s++) {
            mbar_init(fullb  + 8 * s, 256);  // 128 STS-arrives + 128 cp-arrives
            mbar_init(emptyb + 8 * s, 128);  // consumer threads
        }
    }
    __syncthreads();

    if (wid >= 4) {
        // ================= PRODUCERS (warps 4-7, ptid 0..127) =================
        const int ptid = tid - 128;
        const int arow = ptid >> 1;          // A row (64 rows, 2 thr/row)
        const int aq   = ptid & 1;           // 32-float half of the 64-f32 row
        const int brow = ptid;               // B row (128 rows, 1 thr/row)
        const float* asrc0 = A + (long)(m0 + arow) * N_ROWS + aq * 32;
        const unsigned short* bsrc0 = g_xT + (long)brow * N_ROWS;

        float4 af[8];
        auto ldg = [&](int i) {
            const float* s = asrc0 + (long)i * KT2;
            #pragma unroll
            for (int j = 0; j < 8; j++)
                af[j] = *reinterpret_cast<const float4*>(s + j * 4);
        };

        int st = 0, ph = 1;                  // producer starts phase 1
        ldg(0);
        for (int i = 0; i < iters; i++) {
            mbar_wait(emptyb + 8 * st, ph);
            const uint32_t ab = stage0 + st * STG2;
            const uint32_t bb = ab + A2_BYTES;
            // A: fp32 -> fp16, swizzled STS
            #pragma unroll
            for (int j = 0; j < 8; j++) {
                const int c = 4 * aq + (j >> 1);
                const uint32_t addr = ab + arow * 128
                    + ((c ^ (arow & 7)) << 4) + (j & 1) * 8;
                sts64(addr, pack2(af[j].x, af[j].y), pack2(af[j].z, af[j].w));
            }
            mbar_arrive(fullb + 8 * st);     // release: STS visible
            // B: fp16 straight from gmem via cp.async
            const unsigned short* bs = bsrc0 + (long)i * KT2;
            #pragma unroll
            for (int j = 0; j < 8; j++)
                cp16(bb + brow * 128 + ((j ^ (brow & 7)) << 4), bs + j * 8);
            cp_mbar_arrive(fullb + 8 * st);  // arrives when B lands
            if (i + 1 < iters) ldg(i + 1);   // overlap next A with wait
            if (++st == NST2) { st = 0; ph ^= 1; }
        }
    } else {
        // ================= CONSUMERS (warps 0-3, tile 32x64) =================
        const int warpM = (wid & 1) * 32;
        const int warpN = (wid >> 1) * 64;

        float c[2][8][4];
        #pragma unroll
        for (int mi = 0; mi < 2; mi++)
            #pragma unroll
            for (int nj = 0; nj < 8; nj++)
                #pragma unroll
                for (int q = 0; q < 4; q++) c[mi][nj][q] = 0.f;

        const int rowA_l = warpM + (lane & 15);
        const int cpA    = lane >> 4;
        const int rowB_l = warpN + (lane & 7) + 8 * (lane >> 4);
        const int cpB    = (lane >> 3) & 1;

        int st = 0, ph = 0;
        for (int i = 0; i < iters; i++) {
            mbar_wait(fullb + 8 * st, ph);
            const uint32_t ab = stage0 + st * STG2;
            const uint32_t bb = ab + A2_BYTES;
            #pragma unroll
            for (int ks = 0; ks < 4; ks++) {
                uint32_t a[2][4];
                #pragma unroll
                for (int mi = 0; mi < 2; mi++) {
                    const int r = rowA_l + mi * 16;
                    ldsm_x4(a[mi], ab + r * 128 + (((2 * ks + cpA) ^ (r & 7)) << 4));
                }
                uint32_t b[4][4];
                #pragma unroll
                for (int nb = 0; nb < 4; nb++) {
                    const int r = rowB_l + nb * 16;
                    ldsm_x4(b[nb], bb + r * 128 + (((2 * ks + cpB) ^ (r & 7)) << 4));
                }
                #pragma unroll
                for (int mi = 0; mi < 2; mi++)
                    #pragma unroll
                    for (int nb = 0; nb < 4; nb++) {
                        mma16816(c[mi][nb * 2 + 0], a[mi], b[nb][0], b[nb][1]);
                        mma16816(c[mi][nb * 2 + 1], a[mi], b[nb][2], b[nb][3]);
                    }
            }
            mbar_arrive(emptyb + 8 * st);    // frags in regs; stage reusable
            if (++st == NST2) { st = 0; ph ^= 1; }
        }

        // ---- epilogue ----
        const int erow = m0 + warpM + (lane >> 2);
        const int ecol = warpN + (lane & 3) * 2;
        #pragma unroll
        for (int mi = 0; mi < 2; mi++)
            #pragma unroll
            for (int nj = 0; nj < 8; nj++) {
                const long r = erow + mi * 16;
                const int n  = ecol + nj * 8;
                const float* cc = c[mi][nj];
                *reinterpret_cast<float2*>(Out + r * NT2 + n)       = make_float2(cc[0], cc[1]);
                *reinterpret_cast<float2*>(Out + (r + 8) * NT2 + n) = make_float2(cc[2], cc[3]);
            }
    }
}

// ============================================================================
// GEMM1 (R7, proven): xT = (inputs @ W)^T -> g_xT fp16
// ============================================================================
__global__ void __launch_bounds__(256, 2)
gcn_gemm1(const float* __restrict__ A, const float* __restrict__ W)
{
    extern __shared__ char smem[];
    const uint32_t sb = smem_u32(smem);
    const int tid = threadIdx.x;
    const int lane = tid & 31;
    const int wid = tid >> 5;
    const int m0 = blockIdx.x * MT1;
    const int warpM = (wid & 1) * 32;
    const int warpN = (wid >> 1) * 32;
    const int iters = D_IN / KT1;        // 8

    float4 af[4];
    float4 bw[8];
    const int msub = tid >> 4;
    const int kq   = tid & 15;
    const int nq = (tid & 31) * 4;
    const int kk = tid >> 5;

    auto load_regs = [&](int i) {
        const long k0 = (long)i * KT1;
        #pragma unroll
        for (int j = 0; j < 4; j++) {
            const int m = msub + 16 * j;
            af[j] = *reinterpret_cast<const float4*>(A + (long)(m0 + m) * D_IN + k0 + kq * 4);
        }
        #pragma unroll
        for (int j = 0; j < 8; j++) {
            const long k = k0 + kk + 8 * j;
            bw[j] = *reinterpret_cast<const float4*>(W + k * 128 + nq);
        }
    };

    auto produce = [&](int i) {
        const int stage = i % NST1;
        const uint32_t abase = sb + stage * STG1;
        const uint32_t bbase = abase + MT1 * 128;
        #pragma unroll
        for (int j = 0; j < 4; j++) {
            const int m = msub + 16 * j;
            const uint32_t addr = abase + m * 128
                + ((((kq * 4) >> 3) ^ (m & 7)) << 4) + ((kq & 1) << 3);
            sts64(addr, pack2(af[j].x, af[j].y), pack2(af[j].z, af[j].w));
        }
        #pragma unroll
        for (int j = 0; j < 8; j++) {
            const float* f = &bw[j].x;
            #pragma unroll
            for (int q = 0; q < 4; q++) {
                const int n = nq + q;
                const uint32_t addr = bbase + n * 128
                    + ((j ^ (n & 7)) << 4) + (kk << 1);
                sts16(addr, __half_as_ushort(__float2half_rn(f[q])));
            }
        }
    };

    float c[2][4][4];
    #pragma unroll
    for (int mi = 0; mi < 2; mi++)
        #pragma unroll
        for (int nj = 0; nj < 4; nj++)
            #pragma unroll
            for (int q = 0; q < 4; q++) c[mi][nj][q] = 0.f;

    const int rowA  = warpM + (lane & 15);
    const int cpA   = lane >> 4;
    const int rowBb = warpN + (lane & 7) + 8 * (lane >> 4);
    const int rowB7 = rowBb & 7;
    const int cpB   = (lane >> 3) & 1;

    auto compute = [&](int i) {
        const int stage = i % NST1;
        const uint32_t abase = sb + stage * STG1;
        const uint32_t bbase = abase + MT1 * 128;
        #pragma unroll
        for (int ks = 0; ks < 4; ks++) {
            uint32_t a[2][4];
            #pragma unroll
            for (int mi = 0; mi < 2; mi++)
                ldsm_x4(a[mi], abase + (rowA + mi * 16) * 128
                        + (((ks * 2 + cpA) ^ (rowA & 7)) << 4));
            uint32_t b[2][4];
            #pragma unroll
            for (int nbp = 0; nbp < 2; nbp++)
                ldsm_x4(b[nbp], bbase + (rowBb + nbp * 16) * 128
                        + (((ks * 2 + cpB) ^ rowB7) << 4));
            #pragma unroll
            for (int mi = 0; mi < 2; mi++)
                #pragma unroll
                for (int nbp = 0; nbp < 2; nbp++) {
                    mma16816(c[mi][nbp * 2 + 0], a[mi], b[nbp][0], b[nbp][1]);
                    mma16816(c[mi][nbp * 2 + 1], a[mi], b[nbp][2], b[nbp][3]);
                }
        }
    };

    load_regs(0);
    produce(0);
    if (iters > 1) load_regs(1);

    for (int i = 0; i < iters; i++) {
        if (i + 1 < iters) produce(i + 1);
        if (i + 2 < iters) load_regs(i + 2);
        __syncthreads();
        compute(i);
    }

    const int erow = m0 + warpM + (lane >> 2);
    const int ecol = warpN + (lane & 3) * 2;
    #pragma unroll
    for (int mi = 0; mi < 2; mi++) {
        #pragma unroll
        for (int nj = 0; nj < 4; nj++) {
            const int r = erow + mi * 16;
            const int n = ecol + nj * 8;
            const float* cc = c[mi][nj];
            g_xT[(long)n * N_ROWS + r]           = __half_as_ushort(__float2half_rn(cc[0]));
            g_xT[(long)(n + 1) * N_ROWS + r]     = __half_as_ushort(__float2half_rn(cc[1]));
            g_xT[(long)n * N_ROWS + r + 8]       = __half_as_ushort(__float2half_rn(cc[2]));
            g_xT[(long)(n + 1) * N_ROWS + r + 8] = __half_as_ushort(__float2half_rn(cc[3]));
        }
    }
}

// ============================================================================
extern "C" void kernel_launch(void* const* d_in, const int* in_sizes, int n_in,
                              void* d_out, int out_size)
{
    const float* inputs = nullptr;
    const float* adj = nullptr;
    const float* w = nullptr;
    for (int i = 0; i < n_in; i++) {
        if (in_sizes[i] == N_ROWS * D_IN)        inputs = (const float*)d_in[i];
        else if (in_sizes[i] == N_ROWS * N_ROWS) adj    = (const float*)d_in[i];
        else if (in_sizes[i] == D_IN * D_OUT)    w      = (const float*)d_in[i];
    }
    float* out = (float*)d_out;

    cudaFuncSetAttribute(gcn_gemm1,
                         cudaFuncAttributeMaxDynamicSharedMemorySize, SMEM1);
    cudaFuncSetAttribute(gcn_gemm2,
                         cudaFuncAttributeMaxDynamicSharedMemorySize, SMEM2);

    gcn_gemm1<<<N_ROWS / MT1, 256, SMEM1>>>(inputs, w);
    gcn_gemm2<<<N_ROWS / MT2, 256, SMEM2>>>(adj, out);
}